// round 16
// baseline (speedup 1.0000x reference)
#include <cuda_runtime.h>
#include <math.h>
#include <stdint.h>

#define B    8
#define NN   1024
#define CIN  256
#define COUT 256
#define RR   4
#define HH   4
#define ALPHA 0.2f

// -------- scratch --------
__device__ float g_F[(size_t)RR * B * NN * COUT];
__device__ unsigned g_Fhi[(size_t)RR * B * COUT * NN / 2];  // bf16 pairs, [rb][c][j/2]
__device__ unsigned g_Flo[(size_t)RR * B * COUT * NN / 2];
__device__ unsigned g_Xhi[(size_t)B * NN * CIN / 2];        // [m][k/2] bf16 pairs
__device__ unsigned g_Xlo[(size_t)B * NN * CIN / 2];
__device__ unsigned g_Wthi[RR * COUT * CIN / 2];            // [r][n][k/2]
__device__ unsigned g_Wtlo[RR * COUT * CIN / 2];
__device__ float g_E1 [RR * B * HH * NN];
__device__ float g_E2 [RR * B * HH * NN];
__device__ float g_T  [RR * B * HH * NN];
__device__ float g_A1p[RR * B * HH * NN];
__device__ float g_A2p[RR * B * HH * NN];
__device__ float g_A1 [RR * B * HH * NN];
__device__ float g_A2 [RR * B * HH * NN];
__device__ __align__(16) unsigned g_mask[B * NN * RR * (NN / 32)];

#define LIDX(r, b, h, n) ((((r) * B + (b)) * HH + (h)) * NN + (n))

// -------- helpers --------
__device__ __forceinline__ uint32_t smem_u32(const void* p) {
    uint32_t a;
    asm("{ .reg .u64 t; cvta.to.shared.u64 t, %1; cvt.u32.u64 %0, t; }" : "=r"(a) : "l"(p));
    return a;
}
__device__ __forceinline__ uint32_t sw128(uint32_t o) { return o ^ ((o >> 3) & 0x70); }

__device__ __forceinline__ void ldm_x4(unsigned& r0, unsigned& r1, unsigned& r2,
                                       unsigned& r3, uint32_t addr) {
    asm volatile("ldmatrix.sync.aligned.m8n8.x4.shared.b16 {%0,%1,%2,%3}, [%4];"
                 : "=r"(r0), "=r"(r1), "=r"(r2), "=r"(r3) : "r"(addr));
}
__device__ __forceinline__ void mma_bf16(float* c, unsigned a0, unsigned a1,
                                         unsigned a2, unsigned a3,
                                         unsigned b0, unsigned b1) {
    asm("mma.sync.aligned.m16n8k16.row.col.f32.bf16.bf16.f32 "
        "{%0,%1,%2,%3}, {%4,%5,%6,%7}, {%8,%9}, {%0,%1,%2,%3};"
        : "+f"(c[0]), "+f"(c[1]), "+f"(c[2]), "+f"(c[3])
        : "r"(a0), "r"(a1), "r"(a2), "r"(a3), "r"(b0), "r"(b1));
}
__device__ __forceinline__ float pvf(unsigned mw, int bit, float e1, float e2,
                                     float T, float A1, float A2) {
    float p = (e1 > T) ? A1 * e1 : A2 * e2;
    return ((mw >> bit) & 1u) ? p : 0.f;
}
__device__ __forceinline__ void split2(float v0, float v1, unsigned& hi, unsigned& lo) {
    unsigned u0 = __float_as_uint(v0), u1 = __float_as_uint(v1);
    hi = __byte_perm(u0, u1, 0x7632);
    float l0 = v0 - __uint_as_float(u0 & 0xFFFF0000u);
    float l1 = v1 - __uint_as_float(u1 & 0xFFFF0000u);
    lo = __byte_perm(__float_as_uint(l0), __float_as_uint(l1), 0x7632);
}
__device__ __forceinline__ void cpa16(uint32_t dst, const void* src) {
    asm volatile("cp.async.cg.shared.global [%0], [%1], 16;" :: "r"(dst), "l"(src));
}
#define CPA_COMMIT() asm volatile("cp.async.commit_group;" ::: "memory")
#define CPA_WAIT0()  asm volatile("cp.async.wait_group 0;" ::: "memory")

// SMEM layout for k_pv_mma (32-i tile, single-buffered 64-j F chunk)
#define PV_E2   16384
#define PV_MASK 32768
#define PV_FH   36992
#define PV_FL   (PV_FH + 32768)
#define SMEM_PV (PV_FH + 65536)

// SMEM layout for k_gemm_mma (dynamic): AH 0, AL 16K, BH 32K, BL 48K
#define GM_AL   16384
#define GM_BH   32768
#define GM_BL   49152
#define SMEM_GM 65536

// -------- kernel 1a: split X -> bf16 hi/lo pair words [m][k/2] --------
__global__ __launch_bounds__(256) void k_splitX(const float* __restrict__ X) {
    int idx = blockIdx.x * 256 + threadIdx.x;
    float2 v = *(const float2*)(X + (size_t)idx * 2);
    unsigned hi, lo;
    split2(v.x, v.y, hi, lo);
    g_Xhi[idx] = hi;
    g_Xlo[idx] = lo;
}

// -------- kernel 1b: split+transpose W -> [r][n][k/2] bf16 hi/lo --------
__global__ __launch_bounds__(256) void k_splitW(const float* __restrict__ W) {
    int idx = blockIdx.x * 256 + threadIdx.x;
    int kw = idx & 127;
    int n  = (idx >> 7) & 255;
    int r  = idx >> 15;
    float w0 = W[((size_t)r * 256 + 2 * kw) * 256 + n];
    float w1 = W[((size_t)r * 256 + 2 * kw + 1) * 256 + n];
    unsigned hi, lo;
    split2(w0, w1, hi, lo);
    g_Wthi[idx] = hi;
    g_Wtlo[idx] = lo;
}

// -------- kernel 1c: F = X @ W[r] via mma.sync (3-product split, hoisted B) --------
__global__ __launch_bounds__(256, 2) void k_gemm_mma() {
    extern __shared__ __align__(128) char smem[];
    uint32_t sb = smem_u32(smem);
    int tid = threadIdx.x;
    int wid = tid >> 5, lane = tid & 31;
    int g = lane >> 2, c = lane & 3;
    int m0 = blockIdx.x * 128;
    int n0 = blockIdx.y * 128;
    int r  = blockIdx.z;
    int msub = (wid & 3) * 32;
    int nsub = (wid >> 2) * 64;

    float acc[2][8][4];
#pragma unroll
    for (int mi = 0; mi < 2; mi++)
#pragma unroll
        for (int ni = 0; ni < 8; ni++)
#pragma unroll
            for (int q = 0; q < 4; q++) acc[mi][ni][q] = 0.f;

    int srow = tid >> 1, shalf = tid & 1;

    for (int k0 = 0; k0 < CIN; k0 += 64) {
        __syncthreads();
        {
            const uint4* ph = (const uint4*)(g_Xhi + ((size_t)(m0 + srow) * 128 + k0 / 2 + shalf * 16));
            const uint4* pl = (const uint4*)(g_Xlo + ((size_t)(m0 + srow) * 128 + k0 / 2 + shalf * 16));
#pragma unroll
            for (int q = 0; q < 4; q++) {
                uint32_t off = sw128((uint32_t)(srow * 128 + shalf * 64 + q * 16));
                *(uint4*)(smem + off) = ph[q];
                *(uint4*)(smem + GM_AL + off) = pl[q];
            }
        }
        {
            const uint4* ph = (const uint4*)(g_Wthi + ((size_t)(r * 256 + n0 + srow) * 128 + k0 / 2 + shalf * 16));
            const uint4* pl = (const uint4*)(g_Wtlo + ((size_t)(r * 256 + n0 + srow) * 128 + k0 / 2 + shalf * 16));
#pragma unroll
            for (int q = 0; q < 4; q++) {
                uint32_t off = sw128((uint32_t)(srow * 128 + shalf * 64 + q * 16));
                *(uint4*)(smem + GM_BH + off) = ph[q];
                *(uint4*)(smem + GM_BL + off) = pl[q];
            }
        }
        __syncthreads();

#pragma unroll
        for (int ks = 0; ks < 4; ks++) {
            unsigned BH[8][2], BL[8][2];
#pragma unroll
            for (int nip = 0; nip < 4; nip++) {
                int brow = nsub + nip * 16 + (lane & 7) + ((lane >> 4) << 3);
                uint32_t boff = sw128((uint32_t)(brow * 128 + ks * 32 + ((lane >> 3) & 1) * 16));
                ldm_x4(BH[2 * nip][0], BH[2 * nip][1], BH[2 * nip + 1][0], BH[2 * nip + 1][1],
                       sb + GM_BH + boff);
                ldm_x4(BL[2 * nip][0], BL[2 * nip][1], BL[2 * nip + 1][0], BL[2 * nip + 1][1],
                       sb + GM_BL + boff);
            }
#pragma unroll
            for (int mi = 0; mi < 2; mi++) {
                int arow = msub + mi * 16 + (lane & 15);
                uint32_t aoff = sw128((uint32_t)(arow * 128 + ks * 32 + (lane >> 4) * 16));
                unsigned ah0, ah1, ah2, ah3, al0, al1, al2, al3;
                ldm_x4(ah0, ah1, ah2, ah3, sb + aoff);
                ldm_x4(al0, al1, al2, al3, sb + GM_AL + aoff);
#pragma unroll
                for (int ni = 0; ni < 8; ni++) {
                    mma_bf16(acc[mi][ni], ah0, ah1, ah2, ah3, BH[ni][0], BH[ni][1]);
                    mma_bf16(acc[mi][ni], ah0, ah1, ah2, ah3, BL[ni][0], BL[ni][1]);
                    mma_bf16(acc[mi][ni], al0, al1, al2, al3, BH[ni][0], BH[ni][1]);
                }
            }
        }
    }

    float* Fo = g_F + (size_t)r * (B * NN) * COUT;
#pragma unroll
    for (int mi = 0; mi < 2; mi++) {
        int m = m0 + msub + mi * 16 + g;
#pragma unroll
        for (int ni = 0; ni < 8; ni++) {
            int col = n0 + nsub + ni * 8 + 2 * c;
            *(float2*)&Fo[(size_t)m * COUT + col] = make_float2(acc[mi][ni][0], acc[mi][ni][1]);
            *(float2*)&Fo[(size_t)(m + 8) * COUT + col] = make_float2(acc[mi][ni][2], acc[mi][ni][3]);
        }
    }
}

// -------- kernel 1d: transpose+split F -> bf16 hi/lo planes [rb][c][j] --------
__global__ __launch_bounds__(256) void k_split() {
    int rb = blockIdx.z;
    int jt = blockIdx.x;
    int ct = blockIdx.y;
    __shared__ float sm[32][33];
    int t = threadIdx.x;
    {
        int tx = t & 31, ty = t >> 5;
#pragma unroll
        for (int u = 0; u < 4; u++) {
            int jj = ty + u * 8;
            sm[jj][tx] = g_F[((size_t)rb * NN + jt * 32 + jj) * COUT + ct * 32 + tx];
        }
    }
    __syncthreads();
    {
        int tx2 = t & 15, cy = t >> 4;
#pragma unroll
        for (int u = 0; u < 2; u++) {
            int c = cy + u * 16;
            float p0 = sm[2 * tx2][c];
            float p1 = sm[2 * tx2 + 1][c];
            unsigned hiw, low;
            split2(p0, p1, hiw, low);
            size_t idx = ((size_t)rb * 256 + ct * 32 + c) * 512 + jt * 16 + tx2;
            g_Fhi[idx] = hiw;
            g_Flo[idx] = low;
        }
    }
}

// -------- kernel 2: li/lj dots + exp factor tables --------
__global__ __launch_bounds__(256) void k_lvec(const float* __restrict__ a) {
    int warp = threadIdx.x >> 5, lane = threadIdx.x & 31;
    int rbn = blockIdx.x * 8 + warp;
    int r = rbn >> 13;
    int bn = rbn & 8191;
    int b = bn >> 10, n = bn & 1023;
    const float* f = g_F + (size_t)rbn * COUT;
#pragma unroll
    for (int h = 0; h < HH; h++) {
        const float* ah = a + (r * HH + h) * 128;
        float f1 = f[h * 64 + lane];
        float f2 = f[h * 64 + 32 + lane];
        float li = f1 * ah[lane]      + f2 * ah[32 + lane];
        float lj = f1 * ah[64 + lane] + f2 * ah[96 + lane];
#pragma unroll
        for (int o = 16; o > 0; o >>= 1) {
            li += __shfl_xor_sync(~0u, li, o);
            lj += __shfl_xor_sync(~0u, lj, o);
        }
        if (lane == 0) {
            int idx = LIDX(r, b, h, n);
            g_E1[idx]  = expf(lj);
            g_E2[idx]  = expf(ALPHA * lj);
            g_T[idx]   = expf(-li);
            g_A1p[idx] = expf(li);
            g_A2p[idx] = expf(ALPHA * li);
        }
    }
}

// -------- kernel 3a: streaming adjacency bit-pack --------
__global__ __launch_bounds__(256) void k_pack(const int* __restrict__ adj) {
    int w    = (blockIdx.x * 256 + threadIdx.x) >> 5;
    int lane = threadIdx.x & 31;
    int jw = w & 31;
    int i  = (w >> 5) & 1023;
    int b  = w >> 15;
    int j  = jw * 32 + lane;
    const int4 av = *(const int4*)(adj + ((size_t)(b * NN + i) * NN + j) * RR);
    unsigned m0 = __ballot_sync(~0u, av.x != 0);
    unsigned m1 = __ballot_sync(~0u, av.y != 0);
    unsigned m2 = __ballot_sync(~0u, av.z != 0);
    unsigned m3 = __ballot_sync(~0u, av.w != 0);
    if (lane < 4) {
        unsigned mv = (lane == 0) ? m0 : (lane == 1) ? m1 : (lane == 2) ? m2 : m3;
        g_mask[(((size_t)b * NN + i) * RR + lane) * (NN / 32) + jw] = mv;
    }
}

// -------- kernel 3b: softmax denominators from packed bits --------
#define JC 256
__global__ __launch_bounds__(256) void k_denom() {
    int b  = blockIdx.y;
    int i0 = blockIdx.x * 8;
    int warp = threadIdx.x >> 5, lane = threadIdx.x & 31;
    int i = i0 + warp;
    int bn = b * NN + i;
    __shared__ float sE1[16][JC];
    __shared__ float sE2[16][JC];
    float T[16], s1[16], s2[16];
#pragma unroll
    for (int rh = 0; rh < 16; rh++) {
        int r = rh >> 2, h = rh & 3;
        T[rh] = g_T[LIDX(r, b, h, i)];
        s1[rh] = 0.f; s2[rh] = 0.f;
    }
    for (int jc = 0; jc < NN; jc += JC) {
        __syncthreads();
        for (int idx = threadIdx.x; idx < 16 * JC; idx += 256) {
            int rh = idx / JC, jj = idx % JC;
            int r = rh >> 2, h = rh & 3;
            int g = LIDX(r, b, h, jc + jj);
            sE1[rh][jj] = g_E1[g];
            sE2[rh][jj] = g_E2[g];
        }
        __syncthreads();
        for (int js = 0; js < JC; js += 32) {
            int jword = (jc + js) >> 5;
            unsigned mw[4];
#pragma unroll
            for (int r = 0; r < 4; r++)
                mw[r] = g_mask[(((size_t)bn) * RR + r) * (NN / 32) + jword];
#pragma unroll
            for (int rh = 0; rh < 16; rh++) {
                if ((mw[rh >> 2] >> lane) & 1u) {
                    float e1 = sE1[rh][js + lane];
                    float e2 = sE2[rh][js + lane];
                    if (e1 > T[rh]) s1[rh] += e1; else s2[rh] += e2;
                }
            }
        }
    }
#pragma unroll
    for (int rh = 0; rh < 16; rh++) {
#pragma unroll
        for (int o = 16; o > 0; o >>= 1) {
            s1[rh] += __shfl_xor_sync(~0u, s1[rh], o);
            s2[rh] += __shfl_xor_sync(~0u, s2[rh], o);
        }
    }
#pragma unroll
    for (int rh = 0; rh < 16; rh++) {
        if (lane == rh) {
            int r = rh >> 2, h = rh & 3;
            int idx = LIDX(r, b, h, i);
            float A1 = g_A1p[idx], A2 = g_A2p[idx];
            float den = A1 * s1[rh] + A2 * s2[rh];
            if (!(den > 0.f)) { den = 1.f; A1 = 0.f; A2 = 0.f; }
            g_A1[idx] = A1 / den;
            g_A2[idx] = A2 / den;
        }
    }
}

// -------- kernel 4: PV via mma.sync bf16, 32-i tiles, 2 blocks/SM --------
// grid (32, B); 8 warps; warp w: isub = w&1 (16 rows), h = w>>1 (one head)
__global__ __launch_bounds__(256) void k_pv_mma(float* __restrict__ out) {
    extern __shared__ __align__(128) char smem[];
    float* sE1 = (float*)(smem);
    float* sE2 = (float*)(smem + PV_E2);
    unsigned* smask = (unsigned*)(smem + PV_MASK);   // [32][33] padded
    uint32_t sb = smem_u32(smem);

    int b = blockIdx.y, i0 = blockIdx.x * 32;
    int tid = threadIdx.x;
    int wid = tid >> 5, lane = tid & 31;
    int g = lane >> 2, c = lane & 3;
    int isub = wid & 1;
    int h = wid >> 1;
    int rowl = isub * 16 + g;       // local row 0..31
    int rowh = rowl + 8;

    float acc[8][4];
#pragma unroll
    for (int nf = 0; nf < 8; nf++)
#pragma unroll
        for (int q = 0; q < 4; q++) acc[nf][q] = 0.f;

    for (int r = 0; r < RR; r++) {
        int rb = r * B + b;
        __syncthreads();   // all warps done with previous r's tables
#pragma unroll
        for (int u = 0; u < 16; u++) {
            int idx = u * 256 + tid;
            sE1[idx] = g_E1[rb * 4096 + idx];
            sE2[idx] = g_E2[rb * 4096 + idx];
        }
#pragma unroll
        for (int u = 0; u < 4; u++) {
            int idx = u * 256 + tid;
            int row = idx >> 5, w = idx & 31;
            smask[row * 33 + w] =
                g_mask[(((size_t)b * NN + i0 + row) * RR + r) * 32 + w];
        }
        float Tc0, Tc1, A1c0, A1c1, A2c0, A2c1;
        {
            int base = rb * 4096 + h * 1024 + i0;
            Tc0  = g_T [base + rowl];  Tc1  = g_T [base + rowh];
            A1c0 = g_A1[base + rowl];  A1c1 = g_A1[base + rowh];
            A2c0 = g_A2[base + rowl];  A2c1 = g_A2[base + rowh];
        }

        for (int jc = 0; jc < NN; jc += 64) {
            __syncthreads();   // previous chunk consumed (and E staged, 1st iter)
            {
                const uint4* ph = (const uint4*)(g_Fhi + ((size_t)rb * 256 + tid) * 512 + jc / 2);
                const uint4* pl = (const uint4*)(g_Flo + ((size_t)rb * 256 + tid) * 512 + jc / 2);
#pragma unroll
                for (int q = 0; q < 8; q++) {
                    uint32_t off = sw128((uint32_t)(tid * 128 + q * 16));
                    cpa16(sb + PV_FH + off, ph + q);
                    cpa16(sb + PV_FL + off, pl + q);
                }
            }
            CPA_COMMIT();
            CPA_WAIT0();
            __syncthreads();

#pragma unroll
            for (int kf = 0; kf < 4; kf++) {
                int jb = jc + kf * 16;
                unsigned mwl = smask[rowl * 33 + (jb >> 5)];
                unsigned mwh = smask[rowh * 33 + (jb >> 5)];
                int bo = jb & 31;
                int eb = h * 1024 + jb + 2 * c;
                float2 e1a = *(float2*)&sE1[eb];
                float2 e1b = *(float2*)&sE1[eb + 8];
                float2 e2a = *(float2*)&sE2[eb];
                float2 e2b = *(float2*)&sE2[eb + 8];
                float p00 = pvf(mwl, bo + 2*c,     e1a.x, e2a.x, Tc0, A1c0, A2c0);
                float p01 = pvf(mwl, bo + 2*c + 1, e1a.y, e2a.y, Tc0, A1c0, A2c0);
                float p02 = pvf(mwl, bo + 8 + 2*c,     e1b.x, e2b.x, Tc0, A1c0, A2c0);
                float p03 = pvf(mwl, bo + 8 + 2*c + 1, e1b.y, e2b.y, Tc0, A1c0, A2c0);
                float p10 = pvf(mwh, bo + 2*c,     e1a.x, e2a.x, Tc1, A1c1, A2c1);
                float p11 = pvf(mwh, bo + 2*c + 1, e1a.y, e2a.y, Tc1, A1c1, A2c1);
                float p12 = pvf(mwh, bo + 8 + 2*c,     e1b.x, e2b.x, Tc1, A1c1, A2c1);
                float p13 = pvf(mwh, bo + 8 + 2*c + 1, e1b.y, e2b.y, Tc1, A1c1, A2c1);
                unsigned ah0, ah1, ah2, ah3, al0, al1, al2, al3;
                split2(p00, p01, ah0, al0);
                split2(p10, p11, ah1, al1);
                split2(p02, p03, ah2, al2);
                split2(p12, p13, ah3, al3);
#pragma unroll
                for (int nfp = 0; nfp < 4; nfp++) {
                    int lr = h * 64 + nfp * 16 + (lane & 7) + ((lane >> 4) << 3);
                    int jo2 = kf * 32 + ((lane >> 3) & 1) * 16;
                    uint32_t off = sw128((uint32_t)(lr * 128 + jo2));
                    unsigned bh0, bh1, bh2, bh3, bl0, bl1, bl2, bl3;
                    ldm_x4(bh0, bh1, bh2, bh3, sb + PV_FH + off);
                    ldm_x4(bl0, bl1, bl2, bl3, sb + PV_FL + off);
                    mma_bf16(acc[2 * nfp],     ah0, ah1, ah2, ah3, bh0, bh1);
                    mma_bf16(acc[2 * nfp],     ah0, ah1, ah2, ah3, bl0, bl1);
                    mma_bf16(acc[2 * nfp],     al0, al1, al2, al3, bh0, bh1);
                    mma_bf16(acc[2 * nfp + 1], ah0, ah1, ah2, ah3, bh2, bh3);
                    mma_bf16(acc[2 * nfp + 1], ah0, ah1, ah2, ah3, bl2, bl3);
                    mma_bf16(acc[2 * nfp + 1], al0, al1, al2, al3, bh2, bh3);
                }
            }
        }
    }

    // epilogue: direct stores (each output owned by exactly one warp)
#pragma unroll
    for (int nf = 0; nf < 8; nf++) {
        int col = h * 64 + nf * 8 + 2 * c;
        size_t rl = (size_t)(b * NN + i0 + rowl) * 256;
        size_t rh2 = (size_t)(b * NN + i0 + rowh) * 256;
        *(float2*)&out[rl + col]  = make_float2(acc[nf][0], acc[nf][1]);
        *(float2*)&out[rh2 + col] = make_float2(acc[nf][2], acc[nf][3]);
    }
}

// -------- launch --------
extern "C" void kernel_launch(void* const* d_in, const int* in_sizes, int n_in,
                              void* d_out, int out_size) {
    const float* X   = (const float*)d_in[0];
    const int*   adj = (const int*)d_in[1];
    const float* W   = (const float*)d_in[2];
    const float* a   = (const float*)d_in[3];
    float* out = (float*)d_out;

    cudaFuncSetAttribute(k_pv_mma, cudaFuncAttributeMaxDynamicSharedMemorySize, SMEM_PV);
    cudaFuncSetAttribute(k_gemm_mma, cudaFuncAttributeMaxDynamicSharedMemorySize, SMEM_GM);

    k_splitX<<<(B * NN * CIN / 2) / 256, 256>>>(X);
    k_splitW<<<(RR * COUT * CIN / 2) / 256, 256>>>(W);
    k_gemm_mma<<<dim3((B * NN) / 128, 2, RR), 256, SMEM_GM>>>();
    k_split<<<dim3(NN / 32, COUT / 32, RR * B), 256>>>();
    k_lvec<<<(RR * B * NN) / 8, 256>>>(a);
    k_pack<<<(B * NN * 32) / 8, 256>>>(adj);
    k_denom<<<dim3(NN / 8, B), 256>>>();
    k_pv_mma<<<dim3(NN / 32, B), 256, SMEM_PV>>>(out);
}

// round 17
// speedup vs baseline: 1.3400x; 1.3400x over previous
#include <cuda_runtime.h>
#include <math.h>
#include <stdint.h>

#define B    8
#define NN   1024
#define CIN  256
#define COUT 256
#define RR   4
#define HH   4
#define ALPHA 0.2f

// -------- scratch --------
__device__ float g_F[(size_t)RR * B * NN * COUT];
__device__ unsigned g_Fhi[(size_t)RR * B * COUT * NN / 2];  // bf16 pairs, [rb][c][j/2]
__device__ unsigned g_Flo[(size_t)RR * B * COUT * NN / 2];
__device__ unsigned g_Xhi[(size_t)B * NN * CIN / 2];        // [m][k/2] bf16 pairs
__device__ unsigned g_Xlo[(size_t)B * NN * CIN / 2];
__device__ unsigned g_Wthi[RR * COUT * CIN / 2];            // [r][n][k/2]
__device__ unsigned g_Wtlo[RR * COUT * CIN / 2];
__device__ float g_E1 [RR * B * HH * NN];
__device__ float g_E2 [RR * B * HH * NN];
__device__ float g_T  [RR * B * HH * NN];
__device__ float g_A1p[RR * B * HH * NN];
__device__ float g_A2p[RR * B * HH * NN];
__device__ float g_A1 [RR * B * HH * NN];
__device__ float g_A2 [RR * B * HH * NN];
__device__ __align__(16) unsigned g_mask[B * NN * RR * (NN / 32)];

#define LIDX(r, b, h, n) ((((r) * B + (b)) * HH + (h)) * NN + (n))

// -------- helpers --------
__device__ __forceinline__ uint32_t smem_u32(const void* p) {
    uint32_t a;
    asm("{ .reg .u64 t; cvta.to.shared.u64 t, %1; cvt.u32.u64 %0, t; }" : "=r"(a) : "l"(p));
    return a;
}
__device__ __forceinline__ uint32_t sw128(uint32_t o) { return o ^ ((o >> 3) & 0x70); }

__device__ __forceinline__ void ldm_x4(unsigned& r0, unsigned& r1, unsigned& r2,
                                       unsigned& r3, uint32_t addr) {
    asm volatile("ldmatrix.sync.aligned.m8n8.x4.shared.b16 {%0,%1,%2,%3}, [%4];"
                 : "=r"(r0), "=r"(r1), "=r"(r2), "=r"(r3) : "r"(addr));
}
__device__ __forceinline__ void mma_bf16(float* c, unsigned a0, unsigned a1,
                                         unsigned a2, unsigned a3,
                                         unsigned b0, unsigned b1) {
    asm("mma.sync.aligned.m16n8k16.row.col.f32.bf16.bf16.f32 "
        "{%0,%1,%2,%3}, {%4,%5,%6,%7}, {%8,%9}, {%0,%1,%2,%3};"
        : "+f"(c[0]), "+f"(c[1]), "+f"(c[2]), "+f"(c[3])
        : "r"(a0), "r"(a1), "r"(a2), "r"(a3), "r"(b0), "r"(b1));
}
__device__ __forceinline__ float pvf(unsigned mw, int bit, float e1, float e2,
                                     float T, float A1, float A2) {
    float p = (e1 > T) ? A1 * e1 : A2 * e2;
    return ((mw >> bit) & 1u) ? p : 0.f;
}
__device__ __forceinline__ void split2(float v0, float v1, unsigned& hi, unsigned& lo) {
    unsigned u0 = __float_as_uint(v0), u1 = __float_as_uint(v1);
    hi = __byte_perm(u0, u1, 0x7632);
    float l0 = v0 - __uint_as_float(u0 & 0xFFFF0000u);
    float l1 = v1 - __uint_as_float(u1 & 0xFFFF0000u);
    lo = __byte_perm(__float_as_uint(l0), __float_as_uint(l1), 0x7632);
}
__device__ __forceinline__ void cpa16(uint32_t dst, const void* src) {
    asm volatile("cp.async.cg.shared.global [%0], [%1], 16;" :: "r"(dst), "l"(src));
}
#define CPA_COMMIT() asm volatile("cp.async.commit_group;" ::: "memory")
#define CPA_WAIT1()  asm volatile("cp.async.wait_group 1;" ::: "memory")

// SMEM layout for k_pv_mma (64-i tile, double-buffered 64-j F chunk)
#define SM_E2   16384
#define SM_MASK 32768
#define SM_FB   43008
#define FB_STRIDE 65536
#define FB_LO   32768
#define SMEM_PV (43008 + 2 * FB_STRIDE)

// SMEM layout for k_gemm_mma (dynamic): AH 0, AL 16K, BH 32K, BL 48K
#define GM_AL   16384
#define GM_BH   32768
#define GM_BL   49152
#define SMEM_GM 65536

// -------- kernel 1a: split X -> bf16 hi/lo pair words [m][k/2] --------
__global__ __launch_bounds__(256) void k_splitX(const float* __restrict__ X) {
    int idx = blockIdx.x * 256 + threadIdx.x;
    float2 v = *(const float2*)(X + (size_t)idx * 2);
    unsigned hi, lo;
    split2(v.x, v.y, hi, lo);
    g_Xhi[idx] = hi;
    g_Xlo[idx] = lo;
}

// -------- kernel 1b: split+transpose W -> [r][n][k/2] bf16 hi/lo --------
__global__ __launch_bounds__(256) void k_splitW(const float* __restrict__ W) {
    int idx = blockIdx.x * 256 + threadIdx.x;
    int kw = idx & 127;
    int n  = (idx >> 7) & 255;
    int r  = idx >> 15;
    float w0 = W[((size_t)r * 256 + 2 * kw) * 256 + n];
    float w1 = W[((size_t)r * 256 + 2 * kw + 1) * 256 + n];
    unsigned hi, lo;
    split2(w0, w1, hi, lo);
    g_Wthi[idx] = hi;
    g_Wtlo[idx] = lo;
}

// -------- kernel 1c: F = X @ W[r] via mma.sync (3-product split, hoisted B) --------
__global__ __launch_bounds__(256, 2) void k_gemm_mma() {
    extern __shared__ __align__(128) char smem[];
    uint32_t sb = smem_u32(smem);
    int tid = threadIdx.x;
    int wid = tid >> 5, lane = tid & 31;
    int g = lane >> 2, c = lane & 3;
    int m0 = blockIdx.x * 128;
    int n0 = blockIdx.y * 128;
    int r  = blockIdx.z;
    int msub = (wid & 3) * 32;
    int nsub = (wid >> 2) * 64;

    float acc[2][8][4];
#pragma unroll
    for (int mi = 0; mi < 2; mi++)
#pragma unroll
        for (int ni = 0; ni < 8; ni++)
#pragma unroll
            for (int q = 0; q < 4; q++) acc[mi][ni][q] = 0.f;

    int srow = tid >> 1, shalf = tid & 1;

    for (int k0 = 0; k0 < CIN; k0 += 64) {
        __syncthreads();
        {
            const uint4* ph = (const uint4*)(g_Xhi + ((size_t)(m0 + srow) * 128 + k0 / 2 + shalf * 16));
            const uint4* pl = (const uint4*)(g_Xlo + ((size_t)(m0 + srow) * 128 + k0 / 2 + shalf * 16));
#pragma unroll
            for (int q = 0; q < 4; q++) {
                uint32_t off = sw128((uint32_t)(srow * 128 + shalf * 64 + q * 16));
                *(uint4*)(smem + off) = ph[q];
                *(uint4*)(smem + GM_AL + off) = pl[q];
            }
        }
        {
            const uint4* ph = (const uint4*)(g_Wthi + ((size_t)(r * 256 + n0 + srow) * 128 + k0 / 2 + shalf * 16));
            const uint4* pl = (const uint4*)(g_Wtlo + ((size_t)(r * 256 + n0 + srow) * 128 + k0 / 2 + shalf * 16));
#pragma unroll
            for (int q = 0; q < 4; q++) {
                uint32_t off = sw128((uint32_t)(srow * 128 + shalf * 64 + q * 16));
                *(uint4*)(smem + GM_BH + off) = ph[q];
                *(uint4*)(smem + GM_BL + off) = pl[q];
            }
        }
        __syncthreads();

#pragma unroll
        for (int ks = 0; ks < 4; ks++) {
            unsigned BH[8][2], BL[8][2];
#pragma unroll
            for (int nip = 0; nip < 4; nip++) {
                int brow = nsub + nip * 16 + (lane & 7) + ((lane >> 4) << 3);
                uint32_t boff = sw128((uint32_t)(brow * 128 + ks * 32 + ((lane >> 3) & 1) * 16));
                ldm_x4(BH[2 * nip][0], BH[2 * nip][1], BH[2 * nip + 1][0], BH[2 * nip + 1][1],
                       sb + GM_BH + boff);
                ldm_x4(BL[2 * nip][0], BL[2 * nip][1], BL[2 * nip + 1][0], BL[2 * nip + 1][1],
                       sb + GM_BL + boff);
            }
#pragma unroll
            for (int mi = 0; mi < 2; mi++) {
                int arow = msub + mi * 16 + (lane & 15);
                uint32_t aoff = sw128((uint32_t)(arow * 128 + ks * 32 + (lane >> 4) * 16));
                unsigned ah0, ah1, ah2, ah3, al0, al1, al2, al3;
                ldm_x4(ah0, ah1, ah2, ah3, sb + aoff);
                ldm_x4(al0, al1, al2, al3, sb + GM_AL + aoff);
#pragma unroll
                for (int ni = 0; ni < 8; ni++) {
                    mma_bf16(acc[mi][ni], ah0, ah1, ah2, ah3, BH[ni][0], BH[ni][1]);
                    mma_bf16(acc[mi][ni], ah0, ah1, ah2, ah3, BL[ni][0], BL[ni][1]);
                    mma_bf16(acc[mi][ni], al0, al1, al2, al3, BH[ni][0], BH[ni][1]);
                }
            }
        }
    }

    float* Fo = g_F + (size_t)r * (B * NN) * COUT;
#pragma unroll
    for (int mi = 0; mi < 2; mi++) {
        int m = m0 + msub + mi * 16 + g;
#pragma unroll
        for (int ni = 0; ni < 8; ni++) {
            int col = n0 + nsub + ni * 8 + 2 * c;
            *(float2*)&Fo[(size_t)m * COUT + col] = make_float2(acc[mi][ni][0], acc[mi][ni][1]);
            *(float2*)&Fo[(size_t)(m + 8) * COUT + col] = make_float2(acc[mi][ni][2], acc[mi][ni][3]);
        }
    }
}

// -------- kernel 1d: transpose+split F -> bf16 hi/lo planes [rb][c][j] --------
__global__ __launch_bounds__(256) void k_split() {
    int rb = blockIdx.z;
    int jt = blockIdx.x;
    int ct = blockIdx.y;
    __shared__ float sm[32][33];
    int t = threadIdx.x;
    {
        int tx = t & 31, ty = t >> 5;
#pragma unroll
        for (int u = 0; u < 4; u++) {
            int jj = ty + u * 8;
            sm[jj][tx] = g_F[((size_t)rb * NN + jt * 32 + jj) * COUT + ct * 32 + tx];
        }
    }
    __syncthreads();
    {
        int tx2 = t & 15, cy = t >> 4;
#pragma unroll
        for (int u = 0; u < 2; u++) {
            int c = cy + u * 16;
            float p0 = sm[2 * tx2][c];
            float p1 = sm[2 * tx2 + 1][c];
            unsigned hiw, low;
            split2(p0, p1, hiw, low);
            size_t idx = ((size_t)rb * 256 + ct * 32 + c) * 512 + jt * 16 + tx2;
            g_Fhi[idx] = hiw;
            g_Flo[idx] = low;
        }
    }
}

// -------- kernel 2: li/lj dots + exp factor tables --------
__global__ __launch_bounds__(256) void k_lvec(const float* __restrict__ a) {
    int warp = threadIdx.x >> 5, lane = threadIdx.x & 31;
    int rbn = blockIdx.x * 8 + warp;
    int r = rbn >> 13;
    int bn = rbn & 8191;
    int b = bn >> 10, n = bn & 1023;
    const float* f = g_F + (size_t)rbn * COUT;
#pragma unroll
    for (int h = 0; h < HH; h++) {
        const float* ah = a + (r * HH + h) * 128;
        float f1 = f[h * 64 + lane];
        float f2 = f[h * 64 + 32 + lane];
        float li = f1 * ah[lane]      + f2 * ah[32 + lane];
        float lj = f1 * ah[64 + lane] + f2 * ah[96 + lane];
#pragma unroll
        for (int o = 16; o > 0; o >>= 1) {
            li += __shfl_xor_sync(~0u, li, o);
            lj += __shfl_xor_sync(~0u, lj, o);
        }
        if (lane == 0) {
            int idx = LIDX(r, b, h, n);
            g_E1[idx]  = expf(lj);
            g_E2[idx]  = expf(ALPHA * lj);
            g_T[idx]   = expf(-li);
            g_A1p[idx] = expf(li);
            g_A2p[idx] = expf(ALPHA * li);
        }
    }
}

// -------- kernel 3a: streaming adjacency bit-pack --------
__global__ __launch_bounds__(256) void k_pack(const int* __restrict__ adj) {
    int w    = (blockIdx.x * 256 + threadIdx.x) >> 5;
    int lane = threadIdx.x & 31;
    int jw = w & 31;
    int i  = (w >> 5) & 1023;
    int b  = w >> 15;
    int j  = jw * 32 + lane;
    const int4 av = *(const int4*)(adj + ((size_t)(b * NN + i) * NN + j) * RR);
    unsigned m0 = __ballot_sync(~0u, av.x != 0);
    unsigned m1 = __ballot_sync(~0u, av.y != 0);
    unsigned m2 = __ballot_sync(~0u, av.z != 0);
    unsigned m3 = __ballot_sync(~0u, av.w != 0);
    if (lane < 4) {
        unsigned mv = (lane == 0) ? m0 : (lane == 1) ? m1 : (lane == 2) ? m2 : m3;
        g_mask[(((size_t)b * NN + i) * RR + lane) * (NN / 32) + jw] = mv;
    }
}

// -------- kernel 3b: softmax denominators from packed bits --------
#define JC 256
__global__ __launch_bounds__(256) void k_denom() {
    int b  = blockIdx.y;
    int i0 = blockIdx.x * 8;
    int warp = threadIdx.x >> 5, lane = threadIdx.x & 31;
    int i = i0 + warp;
    int bn = b * NN + i;
    __shared__ float sE1[16][JC];
    __shared__ float sE2[16][JC];
    float T[16], s1[16], s2[16];
#pragma unroll
    for (int rh = 0; rh < 16; rh++) {
        int r = rh >> 2, h = rh & 3;
        T[rh] = g_T[LIDX(r, b, h, i)];
        s1[rh] = 0.f; s2[rh] = 0.f;
    }
    for (int jc = 0; jc < NN; jc += JC) {
        __syncthreads();
        for (int idx = threadIdx.x; idx < 16 * JC; idx += 256) {
            int rh = idx / JC, jj = idx % JC;
            int r = rh >> 2, h = rh & 3;
            int g = LIDX(r, b, h, jc + jj);
            sE1[rh][jj] = g_E1[g];
            sE2[rh][jj] = g_E2[g];
        }
        __syncthreads();
        for (int js = 0; js < JC; js += 32) {
            int jword = (jc + js) >> 5;
            unsigned mw[4];
#pragma unroll
            for (int r = 0; r < 4; r++)
                mw[r] = g_mask[(((size_t)bn) * RR + r) * (NN / 32) + jword];
#pragma unroll
            for (int rh = 0; rh < 16; rh++) {
                if ((mw[rh >> 2] >> lane) & 1u) {
                    float e1 = sE1[rh][js + lane];
                    float e2 = sE2[rh][js + lane];
                    if (e1 > T[rh]) s1[rh] += e1; else s2[rh] += e2;
                }
            }
        }
    }
#pragma unroll
    for (int rh = 0; rh < 16; rh++) {
#pragma unroll
        for (int o = 16; o > 0; o >>= 1) {
            s1[rh] += __shfl_xor_sync(~0u, s1[rh], o);
            s2[rh] += __shfl_xor_sync(~0u, s2[rh], o);
        }
    }
#pragma unroll
    for (int rh = 0; rh < 16; rh++) {
        if (lane == rh) {
            int r = rh >> 2, h = rh & 3;
            int idx = LIDX(r, b, h, i);
            float A1 = g_A1p[idx], A2 = g_A2p[idx];
            float den = A1 * s1[rh] + A2 * s2[rh];
            if (!(den > 0.f)) { den = 1.f; A1 = 0.f; A2 = 0.f; }
            g_A1[idx] = A1 / den;
            g_A2[idx] = A2 / den;
        }
    }
}

// -------- kernel 4: PV via mma.sync bf16, 64-i tile, 16 warps, dbl-buffered --------
// grid (16, B); 512 threads; warp w: isub = w&3 (16 rows), h = w>>2 (one head)
__global__ __launch_bounds__(512) void k_pv_mma(float* __restrict__ out) {
    extern __shared__ __align__(128) char smem[];
    float* sE1 = (float*)(smem);
    float* sE2 = (float*)(smem + SM_E2);
    unsigned* smask = (unsigned*)(smem + SM_MASK);   // [64][33] padded
    uint32_t sb = smem_u32(smem);

    int b = blockIdx.y, i0 = blockIdx.x * 64;
    int tid = threadIdx.x;
    int wid = tid >> 5, lane = tid & 31;
    int g = lane >> 2, c = lane & 3;
    int isub = wid & 3;
    int h = wid >> 2;
    int rowl = isub * 16 + g;       // local row 0..63
    int rowh = rowl + 8;

    float acc[8][4];
#pragma unroll
    for (int nf = 0; nf < 8; nf++)
#pragma unroll
        for (int q = 0; q < 4; q++) acc[nf][q] = 0.f;

    float Tc0, Tc1, A1c0, A1c1, A2c0, A2c1;

    int srow = tid >> 1, shalf = tid & 1;

    // prefetch chunk 0
    {
        uint32_t fb = sb + SM_FB;
        const uint4* ph = (const uint4*)(g_Fhi + ((size_t)b * 256 + srow) * 512 + shalf * 16);
        const uint4* pl = (const uint4*)(g_Flo + ((size_t)b * 256 + srow) * 512 + shalf * 16);
#pragma unroll
        for (int q = 0; q < 4; q++) {
            uint32_t off = sw128((uint32_t)(srow * 128 + shalf * 64 + q * 16));
            cpa16(fb + off, ph + q);
            cpa16(fb + FB_LO + off, pl + q);
        }
    }
    CPA_COMMIT();

    for (int ch = 0; ch < 64; ch++) {
        int r = ch >> 4;
        int jc = (ch & 15) * 64;
        int rb = r * B + b;

        if ((ch & 15) == 0) {
            // stage E tables + masks for this r (all warps synced: end of prev iter)
#pragma unroll
            for (int u = 0; u < 8; u++) {
                int idx = u * 512 + tid;
                sE1[idx] = g_E1[rb * 4096 + idx];
                sE2[idx] = g_E2[rb * 4096 + idx];
            }
#pragma unroll
            for (int u = 0; u < 4; u++) {
                int idx = u * 512 + tid;
                int row = idx >> 5, w = idx & 31;
                smask[row * 33 + w] =
                    g_mask[(((size_t)b * NN + i0 + row) * RR + r) * 32 + w];
            }
            {
                int base = rb * 4096 + h * 1024 + i0;
                Tc0  = g_T [base + rowl];  Tc1  = g_T [base + rowh];
                A1c0 = g_A1[base + rowl];  A1c1 = g_A1[base + rowh];
                A2c0 = g_A2[base + rowl];  A2c1 = g_A2[base + rowh];
            }
        }

        // prefetch chunk ch+1 into alternate buffer
        if (ch + 1 < 64) {
            int rbp = ((ch + 1) >> 4) * B + b;
            int jcp = ((ch + 1) & 15) * 64;
            uint32_t fb = sb + SM_FB + ((ch + 1) & 1) * FB_STRIDE;
            const uint4* ph = (const uint4*)(g_Fhi + ((size_t)rbp * 256 + srow) * 512 + jcp / 2 + shalf * 16);
            const uint4* pl = (const uint4*)(g_Flo + ((size_t)rbp * 256 + srow) * 512 + jcp / 2 + shalf * 16);
#pragma unroll
            for (int q = 0; q < 4; q++) {
                uint32_t off = sw128((uint32_t)(srow * 128 + shalf * 64 + q * 16));
                cpa16(fb + off, ph + q);
                cpa16(fb + FB_LO + off, pl + q);
            }
        }
        CPA_COMMIT();
        CPA_WAIT1();          // current chunk's data resident
        __syncthreads();      // + E tables visible when (ch&15)==0

        uint32_t fbc = sb + SM_FB + (ch & 1) * FB_STRIDE;

#pragma unroll
        for (int kf = 0; kf < 4; kf++) {
            int jb = jc + kf * 16;
            unsigned mwl = smask[rowl * 33 + (jb >> 5)];
            unsigned mwh = smask[rowh * 33 + (jb >> 5)];
            int bo = jb & 31;
            int eb = h * 1024 + jb + 2 * c;
            float2 e1a = *(float2*)&sE1[eb];
            float2 e1b = *(float2*)&sE1[eb + 8];
            float2 e2a = *(float2*)&sE2[eb];
            float2 e2b = *(float2*)&sE2[eb + 8];
            float p00 = pvf(mwl, bo + 2*c,     e1a.x, e2a.x, Tc0, A1c0, A2c0);
            float p01 = pvf(mwl, bo + 2*c + 1, e1a.y, e2a.y, Tc0, A1c0, A2c0);
            float p02 = pvf(mwl, bo + 8 + 2*c,     e1b.x, e2b.x, Tc0, A1c0, A2c0);
            float p03 = pvf(mwl, bo + 8 + 2*c + 1, e1b.y, e2b.y, Tc0, A1c0, A2c0);
            float p10 = pvf(mwh, bo + 2*c,     e1a.x, e2a.x, Tc1, A1c1, A2c1);
            float p11 = pvf(mwh, bo + 2*c + 1, e1a.y, e2a.y, Tc1, A1c1, A2c1);
            float p12 = pvf(mwh, bo + 8 + 2*c,     e1b.x, e2b.x, Tc1, A1c1, A2c1);
            float p13 = pvf(mwh, bo + 8 + 2*c + 1, e1b.y, e2b.y, Tc1, A1c1, A2c1);
            unsigned ah0, ah1, ah2, ah3, al0, al1, al2, al3;
            split2(p00, p01, ah0, al0);
            split2(p10, p11, ah1, al1);
            split2(p02, p03, ah2, al2);
            split2(p12, p13, ah3, al3);
#pragma unroll
            for (int nfp = 0; nfp < 4; nfp++) {
                int lr = h * 64 + nfp * 16 + (lane & 7) + ((lane >> 4) << 3);
                int jo2 = kf * 32 + ((lane >> 3) & 1) * 16;
                uint32_t off = sw128((uint32_t)(lr * 128 + jo2));
                unsigned bh0, bh1, bh2, bh3, bl0, bl1, bl2, bl3;
                ldm_x4(bh0, bh1, bh2, bh3, fbc + off);
                ldm_x4(bl0, bl1, bl2, bl3, fbc + FB_LO + off);
                mma_bf16(acc[2 * nfp],     ah0, ah1, ah2, ah3, bh0, bh1);
                mma_bf16(acc[2 * nfp],     ah0, ah1, ah2, ah3, bl0, bl1);
                mma_bf16(acc[2 * nfp],     al0, al1, al2, al3, bh0, bh1);
                mma_bf16(acc[2 * nfp + 1], ah0, ah1, ah2, ah3, bh2, bh3);
                mma_bf16(acc[2 * nfp + 1], ah0, ah1, ah2, ah3, bl2, bl3);
                mma_bf16(acc[2 * nfp + 1], al0, al1, al2, al3, bh2, bh3);
            }
        }
        __syncthreads();   // all warps done with this buffer before it is re-filled
    }

    // epilogue: direct stores (each output owned by exactly one warp)
#pragma unroll
    for (int nf = 0; nf < 8; nf++) {
        int col = h * 64 + nf * 8 + 2 * c;
        size_t rl  = (size_t)(b * NN + i0 + rowl) * 256;
        size_t rh2 = (size_t)(b * NN + i0 + rowh) * 256;
        *(float2*)&out[rl + col]  = make_float2(acc[nf][0], acc[nf][1]);
        *(float2*)&out[rh2 + col] = make_float2(acc[nf][2], acc[nf][3]);
    }
}

// -------- launch --------
extern "C" void kernel_launch(void* const* d_in, const int* in_sizes, int n_in,
                              void* d_out, int out_size) {
    const float* X   = (const float*)d_in[0];
    const int*   adj = (const int*)d_in[1];
    const float* W   = (const float*)d_in[2];
    const float* a   = (const float*)d_in[3];
    float* out = (float*)d_out;

    cudaFuncSetAttribute(k_pv_mma, cudaFuncAttributeMaxDynamicSharedMemorySize, SMEM_PV);
    cudaFuncSetAttribute(k_gemm_mma, cudaFuncAttributeMaxDynamicSharedMemorySize, SMEM_GM);

    k_splitX<<<(B * NN * CIN / 2) / 256, 256>>>(X);
    k_splitW<<<(RR * COUT * CIN / 2) / 256, 256>>>(W);
    k_gemm_mma<<<dim3((B * NN) / 128, 2, RR), 256, SMEM_GM>>>();
    k_split<<<dim3(NN / 32, COUT / 32, RR * B), 256>>>();
    k_lvec<<<(RR * B * NN) / 8, 256>>>(a);
    k_pack<<<(B * NN * 32) / 8, 256>>>(adj);
    k_denom<<<dim3(NN / 8, B), 256>>>();
    k_pv_mma<<<dim3(NN / 64, B), 512, SMEM_PV>>>(out);
}